// round 15
// baseline (speedup 1.0000x reference)
#include <cuda_runtime.h>
#include <cuda_fp16.h>
#include <math.h>
#include <stdint.h>

// ---------------------------------------------------------------------------
// BERT-base forward (B=128, S=64, D=768, H=12, L=12, FF=3072).
// GEMMs: mma.sync (HMMA) plain fp16 1-pass, fp32 accumulators,
//        persistent-CTA (296 = 2/SM) tile loop -> no wave quantization.
// QKV emitted fp16; attention reads fp16, computes fp32.
// Attention / LayerNorm / embedding: fp32 CUDA-core kernels.
// ---------------------------------------------------------------------------

#define B_    128
#define S_    64
#define D_    768
#define H_    12
#define DK_   64
#define FF_   3072
#define L_    12
#define NT_   (B_ * S_)          // 8192 tokens
#define NSM_  148
#define GRID_ (2 * NSM_)         // persistent CTAs

// -------------------- scratch (device globals; no allocs) -------------------
__device__ float g_h   [NT_ * D_];
__device__ float g_h1  [NT_ * D_];
__device__ float g_tmp [NT_ * D_];
__device__ float g_pe  [S_ * D_];

// fp16 activations
__device__ __half g_ah[NT_ * FF_];   // FF1 output
__device__ __half g_sh[NT_ * D_];    // h / ctx / h1 fp16 mirror
__device__ __half g_qh[NT_ * D_];
__device__ __half g_kh[NT_ * D_];
__device__ __half g_vh[NT_ * D_];

// fp16 transposed weights: [L][N][K] layout (K contiguous per row)
__device__ __half g_wq[L_ * D_ * D_];
__device__ __half g_wk[L_ * D_ * D_];
__device__ __half g_wv[L_ * D_ * D_];
__device__ __half g_wo[L_ * D_ * D_];
__device__ __half g_w1[L_ * FF_ * D_];   // [L][3072][768]
__device__ __half g_w2[L_ * D_ * FF_];   // [L][768][3072]

// -------------------- PTX helpers (all arch-agnostic, sm_80+) ---------------
__device__ __forceinline__ uint32_t smem_u32(const void* p) {
    uint32_t a;
    asm("{ .reg .u64 t; cvta.to.shared.u64 t, %1; cvt.u32.u64 %0, t; }"
        : "=r"(a) : "l"(p));
    return a;
}
__device__ __forceinline__ void cp16(uint32_t s, const void* g) {
    asm volatile("cp.async.cg.shared.global [%0], [%1], 16;" :: "r"(s), "l"(g) : "memory");
}
__device__ __forceinline__ void ldsm4(uint32_t& r0, uint32_t& r1, uint32_t& r2,
                                      uint32_t& r3, uint32_t a) {
    asm volatile("ldmatrix.sync.aligned.m8n8.x4.shared.b16 {%0,%1,%2,%3}, [%4];"
                 : "=r"(r0), "=r"(r1), "=r"(r2), "=r"(r3) : "r"(a));
}
__device__ __forceinline__ void mma16816(float* c, const uint32_t* a,
                                         uint32_t b0, uint32_t b1) {
    asm volatile("mma.sync.aligned.m16n8k16.row.col.f32.f16.f16.f32 "
                 "{%0,%1,%2,%3}, {%4,%5,%6,%7}, {%8,%9}, {%0,%1,%2,%3};"
                 : "+f"(c[0]), "+f"(c[1]), "+f"(c[2]), "+f"(c[3])
                 : "r"(a[0]), "r"(a[1]), "r"(a[2]), "r"(a[3]), "r"(b0), "r"(b1));
}

// -------------------- persistent HMMA fp16 GEMM -----------------------------
// C[8192, N] = A[8192, K] @ W[K, N] + bias (+GELU). A, W fp16; W transposed
// to Bt[N, K]. CTA tile 128x128, BK=64. grid = 296 persistent CTAs looping
// over T = gx*gy*nz tiles. Output fp32 (op.c) and/or fp16 (op.oh).
struct BOp { const __half* bt; const float* bias; float* c; __half* oh; };

#define GT_       256
#define BM_       128
#define BN_       128
#define BK_       64
#define TILE_B_   16384u       // 128 rows x 128 bytes
#define STAGE_B_  32768u       // A, B
#define GSMEM_    (2 * 32768)

template <bool GELU>
__global__ __launch_bounds__(GT_, 2)
void gemm_kernel(const __half* __restrict__ A,
                 BOp op0, BOp op1, BOp op2, int K, int N, int gx, int gxy, int T)
{
    extern __shared__ char smem[];
    const uint32_t sb = smem_u32(smem);
    const int tid = threadIdx.x, wid = tid >> 5, l = tid & 31;
    const int wm = wid & 1;          // 2 warps along M
    const int wn = wid >> 1;         // 4 warps along N

    // per-lane ldmatrix addressing components
    const uint32_t swz  = (uint32_t)((l & 7) << 4);
    const int aRowL     = wm * 64 + ((l >> 3) & 1) * 8 + (l & 7);
    const uint32_t aSel = (uint32_t)(((l >> 4) & 1) * 16);
    const int bRowL     = wn * 32 + ((l >> 4) & 1) * 8 + (l & 7);
    const uint32_t bSel = (uint32_t)(((l >> 3) & 1) * 16);

    const int nch = K / BK_;

    for (int t = blockIdx.x; t < T; t += GRID_) {
        const int z  = t / gxy;
        const int r  = t - z * gxy;
        const int ny = r / gx;
        const int nx = r - ny * gx;
        const BOp op = (z == 0) ? op0 : ((z == 1) ? op1 : op2);
        const int m0 = ny * BM_;
        const int n0 = nx * BN_;

        float acc[4][4][4];
        #pragma unroll
        for (int i = 0; i < 4; ++i)
            #pragma unroll
            for (int j = 0; j < 4; ++j)
                #pragma unroll
                for (int e = 0; e < 4; ++e) acc[i][j][e] = 0.0f;

        // ---- async prefetch of one stage (A|B tiles): 8 cp16/thread ----
        auto prefetch = [&](int c, int s) {
            const int kc = c * BK_;
            const uint32_t sbase = sb + (uint32_t)s * STAGE_B_;
            #pragma unroll 4
            for (int g = tid; g < 2048; g += GT_) {
                const int tt  = g >> 10;                 // 0=A, 1=B
                const int idx = g & 1023;
                const int row = idx >> 3, seg = idx & 7;
                const uint32_t sa = sbase + (uint32_t)tt * TILE_B_ + (uint32_t)row * 128
                                  + (((uint32_t)(seg * 16)) ^ ((uint32_t)(row & 7) << 4));
                const __half* src;
                if (tt == 0) src = A     + (size_t)(m0 + row) * K + kc + seg * 8;
                else         src = op.bt + (size_t)(n0 + row) * K + kc + seg * 8;
                cp16(sa, src);
            }
            asm volatile("cp.async.commit_group;" ::: "memory");
        };

        prefetch(0, 0);

        for (int c = 0; c < nch; ++c) {
            if (c + 1 < nch) {
                prefetch(c + 1, (c + 1) & 1);
                asm volatile("cp.async.wait_group 1;" ::: "memory");
            } else {
                asm volatile("cp.async.wait_group 0;" ::: "memory");
            }
            __syncthreads();

            const uint32_t sbase = sb + (uint32_t)(c & 1) * STAGE_B_;
            #pragma unroll
            for (int ks = 0; ks < 4; ++ks) {
                const uint32_t aCol = ((uint32_t)(ks * 32) + aSel) ^ swz;
                const uint32_t bCol = ((uint32_t)(ks * 32) + bSel) ^ swz;
                uint32_t a[4][4];
                #pragma unroll
                for (int mb = 0; mb < 4; ++mb)
                    ldsm4(a[mb][0], a[mb][1], a[mb][2], a[mb][3],
                          sbase + (uint32_t)(aRowL + mb * 16) * 128 + aCol);
                #pragma unroll
                for (int nb = 0; nb < 2; ++nb) {
                    uint32_t b0, b1, b2, b3;
                    ldsm4(b0, b1, b2, b3,
                          sbase + TILE_B_ + (uint32_t)(bRowL + nb * 16) * 128 + bCol);
                    #pragma unroll
                    for (int mb = 0; mb < 4; ++mb) {
                        mma16816(acc[mb][nb * 2 + 0], a[mb], b0, b1);
                        mma16816(acc[mb][nb * 2 + 1], a[mb], b2, b3);
                    }
                }
            }
            __syncthreads();
        }

        // ---- epilogue: bias (+GELU), fp32 and/or fp16 stores ----
        const int rbase = m0 + wm * 64 + (l >> 2);
        const int cbase = n0 + wn * 32 + (l & 3) * 2;
        #pragma unroll
        for (int mb = 0; mb < 4; ++mb) {
            #pragma unroll
            for (int nblk = 0; nblk < 4; ++nblk) {
                const int col = cbase + nblk * 8;
                const float bx = op.bias[col], by = op.bias[col + 1];
                float v[4] = { acc[mb][nblk][0] + bx, acc[mb][nblk][1] + by,
                               acc[mb][nblk][2] + bx, acc[mb][nblk][3] + by };
                if (GELU) {
                    #pragma unroll
                    for (int e = 0; e < 4; ++e)
                        v[e] = 0.5f * v[e] * (1.0f + erff(v[e] * 0.70710678118654752440f));
                }
                const int row = rbase + mb * 16;
                if (op.c) {
                    float2 lo; lo.x = v[0]; lo.y = v[1];
                    float2 hi; hi.x = v[2]; hi.y = v[3];
                    *(float2*)(op.c + (size_t)row * N + col)       = lo;
                    *(float2*)(op.c + (size_t)(row + 8) * N + col) = hi;
                }
                if (op.oh) {
                    __half2 h0, h1;
                    h0.x = __float2half_rn(v[0]);
                    h0.y = __float2half_rn(v[1]);
                    h1.x = __float2half_rn(v[2]);
                    h1.y = __float2half_rn(v[3]);
                    *(__half2*)(op.oh + (size_t)row * N + col)       = h0;
                    *(__half2*)(op.oh + (size_t)(row + 8) * N + col) = h1;
                }
            }
        }
    }
}

// -------------------- weight transpose -> fp16 ------------------------------
__global__ void wtrans_kernel(const float* __restrict__ W,
                              __half* __restrict__ th, int Kd, int Nd)
{
    __shared__ float t[32][33];
    const size_t lo_ = (size_t)blockIdx.z * Kd * Nd;
    const float* Wp = W + lo_;
    __half* thp = th + lo_;
    const int n0 = blockIdx.x * 32, k0 = blockIdx.y * 32;
    const int tx = threadIdx.x & 31, ty = threadIdx.x >> 5;

    #pragma unroll
    for (int j = 0; j < 32; j += 8)
        t[ty + j][tx] = Wp[(size_t)(k0 + ty + j) * Nd + n0 + tx];
    __syncthreads();
    #pragma unroll
    for (int j = 0; j < 32; j += 8)
        thp[(size_t)(n0 + ty + j) * Kd + k0 + tx] = __float2half_rn(t[tx][ty + j]);
}

// fused transpose for the four DxD weight families (one launch)
struct W4 { const float* w; __half* th; };
__global__ void wtrans4_kernel(W4 a, W4 b, W4 c, W4 d)
{
    __shared__ float t[32][33];
    const int which = blockIdx.z & 3;
    const int lyr   = blockIdx.z >> 2;
    const W4 s = (which == 0) ? a : (which == 1) ? b : (which == 2) ? c : d;
    const size_t lo_ = (size_t)lyr * D_ * D_;
    const float* Wp = s.w + lo_;
    __half* thp = s.th + lo_;
    const int n0 = blockIdx.x * 32, k0 = blockIdx.y * 32;
    const int tx = threadIdx.x & 31, ty = threadIdx.x >> 5;

    #pragma unroll
    for (int j = 0; j < 32; j += 8)
        t[ty + j][tx] = Wp[(size_t)(k0 + ty + j) * D_ + n0 + tx];
    __syncthreads();
    #pragma unroll
    for (int j = 0; j < 32; j += 8)
        thp[(size_t)(n0 + ty + j) * D_ + k0 + tx] = __float2half_rn(t[tx][ty + j]);
}

// -------------------- positional-encoding table (flat) ----------------------
__global__ void pe_kernel(float* __restrict__ pe)
{
    const int i = blockIdx.x * 256 + threadIdx.x;
    if (i >= S_ * D_) return;
    const int s = i / D_, c = i - s * D_;
    const int j = c >> 1;
    const double e   = (double)(4 * j) / 768.0;
    const double inv = pow(10000.0, -e);
    const float  arg = (float)((double)s * inv);
    pe[i] = (c & 1) ? cosf(arg) : sinf(arg);
}

// -------------------- embedding (fp32 + fp16) -------------------------------
__global__ void embed_kernel(const int* __restrict__ x, const int* __restrict__ seg,
                             const float* __restrict__ tok, const float* __restrict__ se,
                             const float* __restrict__ pe, float* __restrict__ h,
                             __half* __restrict__ sh)
{
    const int t   = blockIdx.x;
    const int tid = threadIdx.x;
    const int s   = t & (S_ - 1);
    const int xi  = x[t];
    const int si  = seg[t];
    const size_t base = (size_t)t * D_;
    #pragma unroll
    for (int u = 0; u < 3; ++u) {
        const int c = tid + u * 256;
        const float v = tok[(size_t)xi * D_ + c] + se[(size_t)si * D_ + c] + pe[s * D_ + c];
        h[base + c] = v;
        sh[base + c] = __float2half_rn(v);
    }
}

// -------------------- fused attention (fp16 in, fp32 math, fp16 out) --------
// grid = B*H (1536), block = 256. Smem reuse: Qs->P, Ks->V after score phase.
__global__ void attn_fused_kernel(const __half* __restrict__ q, const __half* __restrict__ k,
                                  const __half* __restrict__ v, const int* __restrict__ x,
                                  __half* __restrict__ oh)
{
    __shared__ float Qs[S_ * 65];     // phase 1: Q      phase 2: P
    __shared__ float Ks[S_ * 65];     // phase 1: K      phase 2: V (flat 64-stride)
    __shared__ int   mk[S_];

    const int bh = blockIdx.x;
    const int b  = bh / H_;
    const int h  = bh % H_;
    const int tid = threadIdx.x;

    const __half* qbase = q + (size_t)(b * S_) * D_ + h * DK_;
    const __half* kbase = k + (size_t)(b * S_) * D_ + h * DK_;
    const __half* vbase = v + (size_t)(b * S_) * D_ + h * DK_;

    for (int idx = tid; idx < S_ * DK_; idx += 256) {
        const int r = idx >> 6, d = idx & 63;
        Qs[r * 65 + d] = __half2float(qbase[(size_t)r * D_ + d]);
        Ks[r * 65 + d] = __half2float(kbase[(size_t)r * D_ + d]);
    }
    if (tid < S_) mk[tid] = x[b * S_ + tid];
    __syncthreads();

    const int row = tid >> 2;          // query row 0..63
    const int jc  = (tid & 3) * 16;    // key-col block

    float sc[16];
    #pragma unroll
    for (int jj = 0; jj < 16; ++jj) sc[jj] = 0.0f;

    for (int d = 0; d < DK_; ++d) {
        const float qv = Qs[row * 65 + d];
        #pragma unroll
        for (int jj = 0; jj < 16; ++jj)
            sc[jj] += qv * Ks[(jc + jj) * 65 + d];
    }

    float mx = -3.0e38f;
    #pragma unroll
    for (int jj = 0; jj < 16; ++jj) {
        const float val = (mk[jc + jj] > 0) ? sc[jj] * 0.125f : -1.0e9f;
        sc[jj] = val;
        mx = fmaxf(mx, val);
    }
    mx = fmaxf(mx, __shfl_xor_sync(0xffffffffu, mx, 1));
    mx = fmaxf(mx, __shfl_xor_sync(0xffffffffu, mx, 2));

    float sum = 0.0f;
    #pragma unroll
    for (int jj = 0; jj < 16; ++jj) {
        sc[jj] = expf(sc[jj] - mx);
        sum += sc[jj];
    }
    sum += __shfl_xor_sync(0xffffffffu, sum, 1);
    sum += __shfl_xor_sync(0xffffffffu, sum, 2);
    const float pinv = 1.0f / sum;

    __syncthreads();   // all Qs/Ks reads of phase 1 complete

    // write P into Qs, load V into Ks (flat, stride 64)
    #pragma unroll
    for (int jj = 0; jj < 16; ++jj) Qs[row * 65 + jc + jj] = sc[jj] * pinv;
    for (int idx = tid; idx < S_ * DK_; idx += 256)
        Ks[idx] = __half2float(vbase[(size_t)(idx >> 6) * D_ + (idx & 63)]);
    __syncthreads();

    // ctx = P @ V : thread owns (row, 16 headdims at d0)
    const int d0 = (tid & 3) * 16;
    float acc[16];
    #pragma unroll
    for (int dd = 0; dd < 16; ++dd) acc[dd] = 0.0f;

    for (int j = 0; j < S_; ++j) {
        const float p = Qs[row * 65 + j];
        #pragma unroll
        for (int dd = 0; dd < 16; ++dd)
            acc[dd] += p * Ks[j * DK_ + d0 + dd];
    }

    const size_t obase = (size_t)(b * S_ + row) * D_ + h * DK_ + d0;
    #pragma unroll
    for (int dd = 0; dd < 16; dd += 2) {
        __half2 hb;
        hb.x = __float2half_rn(acc[dd]);
        hb.y = __float2half_rn(acc[dd + 1]);
        *(__half2*)(oh + obase + dd) = hb;
    }
}

// -------------------- residual add + layernorm (fp32 + fp16) ----------------
__global__ void resid_ln_kernel(const float* __restrict__ a, const float* __restrict__ r,
                                const float* __restrict__ g, const float* __restrict__ be,
                                float* __restrict__ out, __half* __restrict__ oh)
{
    const int t   = blockIdx.x;
    const int tid = threadIdx.x;
    const size_t base = (size_t)t * D_;

    const float y0 = a[base + tid]       + r[base + tid];
    const float y1 = a[base + tid + 256] + r[base + tid + 256];
    const float y2 = a[base + tid + 512] + r[base + tid + 512];

    __shared__ float red[256];
    red[tid] = y0 + y1 + y2;
    __syncthreads();
    #pragma unroll
    for (int o = 128; o > 0; o >>= 1) {
        if (tid < o) red[tid] += red[tid + o];
        __syncthreads();
    }
    const float mu = red[0] * (1.0f / 768.0f);
    __syncthreads();

    const float d0 = y0 - mu, d1 = y1 - mu, d2 = y2 - mu;
    red[tid] = d0 * d0 + d1 * d1 + d2 * d2;
    __syncthreads();
    #pragma unroll
    for (int o = 128; o > 0; o >>= 1) {
        if (tid < o) red[tid] += red[tid + o];
        __syncthreads();
    }
    const float var = red[0] * (1.0f / 768.0f);
    const float inv = rsqrtf(var + 1e-5f);

    const float o0 = d0 * inv * g[tid]       + be[tid];
    const float o1 = d1 * inv * g[tid + 256] + be[tid + 256];
    const float o2 = d2 * inv * g[tid + 512] + be[tid + 512];
    out[base + tid]       = o0;
    out[base + tid + 256] = o1;
    out[base + tid + 512] = o2;
    oh[base + tid]        = __float2half_rn(o0);
    oh[base + tid + 256]  = __float2half_rn(o1);
    oh[base + tid + 512]  = __float2half_rn(o2);
}

// ---------------------------------------------------------------------------
extern "C" void kernel_launch(void* const* d_in, const int* in_sizes, int n_in,
                              void* d_out, int out_size)
{
    const int*   x    = (const int*)  d_in[0];
    const int*   seg  = (const int*)  d_in[1];
    const float* tok  = (const float*)d_in[2];
    const float* se   = (const float*)d_in[3];
    const float* Wq   = (const float*)d_in[4];
    const float* bq   = (const float*)d_in[5];
    const float* Wk   = (const float*)d_in[6];
    const float* bk   = (const float*)d_in[7];
    const float* Wv   = (const float*)d_in[8];
    const float* bv   = (const float*)d_in[9];
    const float* Wo   = (const float*)d_in[10];
    const float* bo   = (const float*)d_in[11];
    const float* lng  = (const float*)d_in[12];
    const float* lnb  = (const float*)d_in[13];
    const float* W1   = (const float*)d_in[14];
    const float* b1   = (const float*)d_in[15];
    const float* W2   = (const float*)d_in[16];
    const float* b2   = (const float*)d_in[17];
    float* out = (float*)d_out;

    float *h, *h1, *tmp, *pe;
    __half *ah, *sh, *qh, *kh, *vh;
    __half *wq, *wk, *wv, *wo, *w1, *w2;
    cudaGetSymbolAddress((void**)&h,   g_h);
    cudaGetSymbolAddress((void**)&h1,  g_h1);
    cudaGetSymbolAddress((void**)&tmp, g_tmp);
    cudaGetSymbolAddress((void**)&pe,  g_pe);
    cudaGetSymbolAddress((void**)&ah,  g_ah);
    cudaGetSymbolAddress((void**)&sh,  g_sh);
    cudaGetSymbolAddress((void**)&qh,  g_qh);
    cudaGetSymbolAddress((void**)&kh,  g_kh);
    cudaGetSymbolAddress((void**)&vh,  g_vh);
    cudaGetSymbolAddress((void**)&wq,  g_wq);
    cudaGetSymbolAddress((void**)&wk,  g_wk);
    cudaGetSymbolAddress((void**)&wv,  g_wv);
    cudaGetSymbolAddress((void**)&wo,  g_wo);
    cudaGetSymbolAddress((void**)&w1,  g_w1);
    cudaGetSymbolAddress((void**)&w2,  g_w2);

    cudaFuncSetAttribute(gemm_kernel<false>, cudaFuncAttributeMaxDynamicSharedMemorySize, GSMEM_);
    cudaFuncSetAttribute(gemm_kernel<true >, cudaFuncAttributeMaxDynamicSharedMemorySize, GSMEM_);

    // ---- setup ----
    {
        W4 aq = { Wq, wq }, ak = { Wk, wk }, av = { Wv, wv }, ao = { Wo, wo };
        wtrans4_kernel<<<dim3(24, 24, 4 * L_), 256>>>(aq, ak, av, ao);
    }
    wtrans_kernel<<<dim3(96, 24, L_), 256>>>(W1, w1, D_, FF_);
    wtrans_kernel<<<dim3(24, 96, L_), 256>>>(W2, w2, FF_, D_);
    pe_kernel<<<(S_ * D_ + 255) / 256, 256>>>(pe);
    embed_kernel<<<NT_, 256>>>(x, seg, tok, se, pe, h, sh);

    for (int l = 0; l < L_; ++l) {
        const size_t wOff  = (size_t)l * D_ * D_;
        const size_t fOff1 = (size_t)l * D_ * FF_;
        const size_t fOff2 = (size_t)l * FF_ * D_;

        {   // QKV from fp16 h -> fp16 q/k/v
            BOp oq = { wq + wOff, bq + l * D_, nullptr, qh };
            BOp ok = { wk + wOff, bk + l * D_, nullptr, kh };
            BOp ov = { wv + wOff, bv + l * D_, nullptr, vh };
            gemm_kernel<false><<<GRID_, GT_, GSMEM_>>>(sh, oq, ok, ov,
                                                       D_, D_, 6, 6 * 64, 1152);
        }

        attn_fused_kernel<<<B_ * H_, 256>>>(qh, kh, vh, x, sh);   // fp16 ctx

        {   // O projection from fp16 ctx -> fp32 tmp
            BOp oo = { wo + wOff, bo + l * D_, tmp, nullptr };
            gemm_kernel<false><<<GRID_, GT_, GSMEM_>>>(sh, oo, oo, oo,
                                                       D_, D_, 6, 6 * 64, 384);
        }
        resid_ln_kernel<<<NT_, 256>>>(tmp, h, lng + l * D_, lnb + l * D_, h1, sh);

        {   // FF1 (+GELU) from fp16 h1 -> fp16 ff
            BOp o1 = { w1 + fOff1, b1 + l * FF_, nullptr, ah };
            gemm_kernel<true><<<GRID_, GT_, GSMEM_>>>(sh, o1, o1, o1,
                                                      D_, FF_, 24, 24 * 64, 1536);
        }
        {   // FF2 from fp16 ff -> fp32 tmp
            BOp o2 = { w2 + fOff2, b2 + l * D_, tmp, nullptr };
            gemm_kernel<false><<<GRID_, GT_, GSMEM_>>>(ah, o2, o2, o2,
                                                       FF_, D_, 6, 6 * 64, 384);
        }

        float* dst = (l == L_ - 1) ? out : h;
        resid_ln_kernel<<<NT_, 256>>>(tmp, h1, lng + l * D_, lnb + l * D_, dst, sh);
    }
}

// round 16
// speedup vs baseline: 1.0526x; 1.0526x over previous
#include <cuda_runtime.h>
#include <cuda_fp16.h>
#include <math.h>
#include <stdint.h>

// ---------------------------------------------------------------------------
// BERT-base forward (B=128, S=64, D=768, H=12, L=12, FF=3072).
// GEMMs: mma.sync (HMMA) plain fp16 1-pass, fp32 accumulators.
// Non-persistent grid (R13 proven geometry: 256 thr, 128x128x64, 2-stage,
// 2 CTAs/SM). QKV emitted fp16; attention reads fp16, computes fp32.
// Attention / LayerNorm / embedding: fp32 CUDA-core kernels.
// ---------------------------------------------------------------------------

#define B_    128
#define S_    64
#define D_    768
#define H_    12
#define DK_   64
#define FF_   3072
#define L_    12
#define NT_   (B_ * S_)          // 8192 tokens

// -------------------- scratch (device globals; no allocs) -------------------
__device__ float g_h   [NT_ * D_];
__device__ float g_h1  [NT_ * D_];
__device__ float g_tmp [NT_ * D_];
__device__ float g_pe  [S_ * D_];

// fp16 activations
__device__ __half g_ah[NT_ * FF_];   // FF1 output
__device__ __half g_sh[NT_ * D_];    // h / ctx / h1 fp16 mirror
__device__ __half g_qh[NT_ * D_];
__device__ __half g_kh[NT_ * D_];
__device__ __half g_vh[NT_ * D_];

// fp16 transposed weights: [L][N][K] layout (K contiguous per row)
__device__ __half g_wq[L_ * D_ * D_];
__device__ __half g_wk[L_ * D_ * D_];
__device__ __half g_wv[L_ * D_ * D_];
__device__ __half g_wo[L_ * D_ * D_];
__device__ __half g_w1[L_ * FF_ * D_];   // [L][3072][768]
__device__ __half g_w2[L_ * D_ * FF_];   // [L][768][3072]

// -------------------- PTX helpers (all arch-agnostic, sm_80+) ---------------
__device__ __forceinline__ uint32_t smem_u32(const void* p) {
    uint32_t a;
    asm("{ .reg .u64 t; cvta.to.shared.u64 t, %1; cvt.u32.u64 %0, t; }"
        : "=r"(a) : "l"(p));
    return a;
}
__device__ __forceinline__ void cp16(uint32_t s, const void* g) {
    asm volatile("cp.async.cg.shared.global [%0], [%1], 16;" :: "r"(s), "l"(g) : "memory");
}
__device__ __forceinline__ void ldsm4(uint32_t& r0, uint32_t& r1, uint32_t& r2,
                                      uint32_t& r3, uint32_t a) {
    asm volatile("ldmatrix.sync.aligned.m8n8.x4.shared.b16 {%0,%1,%2,%3}, [%4];"
                 : "=r"(r0), "=r"(r1), "=r"(r2), "=r"(r3) : "r"(a));
}
__device__ __forceinline__ void mma16816(float* c, const uint32_t* a,
                                         uint32_t b0, uint32_t b1) {
    asm volatile("mma.sync.aligned.m16n8k16.row.col.f32.f16.f16.f32 "
                 "{%0,%1,%2,%3}, {%4,%5,%6,%7}, {%8,%9}, {%0,%1,%2,%3};"
                 : "+f"(c[0]), "+f"(c[1]), "+f"(c[2]), "+f"(c[3])
                 : "r"(a[0]), "r"(a[1]), "r"(a[2]), "r"(a[3]), "r"(b0), "r"(b1));
}

// -------------------- HMMA fp16 1-pass GEMM ---------------------------------
// C[8192, N] = A[8192, K] @ W[K, N] + bias (+GELU). A, W fp16; W transposed
// to Bt[N, K]. CTA tile 128x128, BK=64. Output fp32 (op.c) and/or fp16 (op.oh).
struct BOp { const __half* bt; const float* bias; float* c; __half* oh; };

#define GT_       256
#define BM_       128
#define BN_       128
#define BK_       64
#define TILE_B_   16384u       // 128 rows x 128 bytes
#define STAGE_B_  32768u       // A, B
#define GSMEM_    (2 * 32768)

template <bool GELU>
__global__ __launch_bounds__(GT_, 2)
void gemm_kernel(const __half* __restrict__ A,
                 BOp op0, BOp op1, BOp op2, int K, int N)
{
    extern __shared__ char smem[];
    const uint32_t sb = smem_u32(smem);
    const int tid = threadIdx.x, wid = tid >> 5, l = tid & 31;
    const int wm = wid & 1;          // 2 warps along M
    const int wn = wid >> 1;         // 4 warps along N
    const BOp op = (blockIdx.z == 0) ? op0 : ((blockIdx.z == 1) ? op1 : op2);
    const int m0 = blockIdx.y * BM_;
    const int n0 = blockIdx.x * BN_;

    // per-lane ldmatrix addressing components
    const uint32_t swz  = (uint32_t)((l & 7) << 4);
    const int aRow0     = wm * 64 + ((l >> 3) & 1) * 8 + (l & 7);
    const uint32_t aSel = (uint32_t)(((l >> 4) & 1) * 16);
    const int bRow0     = wn * 32 + ((l >> 4) & 1) * 8 + (l & 7);
    const uint32_t bSel = (uint32_t)(((l >> 3) & 1) * 16);

    float acc[4][4][4];
    #pragma unroll
    for (int i = 0; i < 4; ++i)
        #pragma unroll
        for (int j = 0; j < 4; ++j)
            #pragma unroll
            for (int e = 0; e < 4; ++e) acc[i][j][e] = 0.0f;

    const int nch = K / BK_;

    // ---- async prefetch of one stage (A|B tiles): 8 cp16/thread ----
    auto prefetch = [&](int c, int s) {
        const int kc = c * BK_;
        const uint32_t sbase = sb + (uint32_t)s * STAGE_B_;
        #pragma unroll 4
        for (int g = tid; g < 2048; g += GT_) {
            const int t   = g >> 10;                 // 0=A, 1=B
            const int idx = g & 1023;
            const int row = idx >> 3, seg = idx & 7;
            const uint32_t sa = sbase + (uint32_t)t * TILE_B_ + (uint32_t)row * 128
                              + (((uint32_t)(seg * 16)) ^ ((uint32_t)(row & 7) << 4));
            const __half* src;
            if (t == 0) src = A     + (size_t)(m0 + row) * K + kc + seg * 8;
            else        src = op.bt + (size_t)(n0 + row) * K + kc + seg * 8;
            cp16(sa, src);
        }
        asm volatile("cp.async.commit_group;" ::: "memory");
    };

    prefetch(0, 0);

    for (int c = 0; c < nch; ++c) {
        if (c + 1 < nch) {
            prefetch(c + 1, (c + 1) & 1);
            asm volatile("cp.async.wait_group 1;" ::: "memory");
        } else {
            asm volatile("cp.async.wait_group 0;" ::: "memory");
        }
        __syncthreads();

        const uint32_t sbase = sb + (uint32_t)(c & 1) * STAGE_B_;
        #pragma unroll
        for (int ks = 0; ks < 4; ++ks) {
            const uint32_t aCol = ((uint32_t)(ks * 32) + aSel) ^ swz;
            const uint32_t bCol = ((uint32_t)(ks * 32) + bSel) ^ swz;
            uint32_t a[4][4];
            #pragma unroll
            for (int mb = 0; mb < 4; ++mb)
                ldsm4(a[mb][0], a[mb][1], a[mb][2], a[mb][3],
                      sbase + (uint32_t)(aRow0 + mb * 16) * 128 + aCol);
            #pragma unroll
            for (int nb = 0; nb < 2; ++nb) {
                uint32_t b0, b1, b2, b3;
                ldsm4(b0, b1, b2, b3,
                      sbase + TILE_B_ + (uint32_t)(bRow0 + nb * 16) * 128 + bCol);
                #pragma unroll
                for (int mb = 0; mb < 4; ++mb) {
                    mma16816(acc[mb][nb * 2 + 0], a[mb], b0, b1);
                    mma16816(acc[mb][nb * 2 + 1], a[mb], b2, b3);
                }
            }
        }
        __syncthreads();
    }

    // ---- epilogue: bias (+GELU), fp32 and/or fp16 stores ----
    const int rbase = m0 + wm * 64 + (l >> 2);
    const int cbase = n0 + wn * 32 + (l & 3) * 2;
    #pragma unroll
    for (int mb = 0; mb < 4; ++mb) {
        #pragma unroll
        for (int nblk = 0; nblk < 4; ++nblk) {
            const int col = cbase + nblk * 8;
            const float bx = op.bias[col], by = op.bias[col + 1];
            float v[4] = { acc[mb][nblk][0] + bx, acc[mb][nblk][1] + by,
                           acc[mb][nblk][2] + bx, acc[mb][nblk][3] + by };
            if (GELU) {
                #pragma unroll
                for (int e = 0; e < 4; ++e)
                    v[e] = 0.5f * v[e] * (1.0f + erff(v[e] * 0.70710678118654752440f));
            }
            const int row = rbase + mb * 16;
            if (op.c) {
                float2 lo; lo.x = v[0]; lo.y = v[1];
                float2 hi; hi.x = v[2]; hi.y = v[3];
                *(float2*)(op.c + (size_t)row * N + col)       = lo;
                *(float2*)(op.c + (size_t)(row + 8) * N + col) = hi;
            }
            if (op.oh) {
                __half2 h0, h1;
                h0.x = __float2half_rn(v[0]);
                h0.y = __float2half_rn(v[1]);
                h1.x = __float2half_rn(v[2]);
                h1.y = __float2half_rn(v[3]);
                *(__half2*)(op.oh + (size_t)row * N + col)       = h0;
                *(__half2*)(op.oh + (size_t)(row + 8) * N + col) = h1;
            }
        }
    }
}

// -------------------- weight transpose -> fp16 ------------------------------
__global__ void wtrans_kernel(const float* __restrict__ W,
                              __half* __restrict__ th, int Kd, int Nd)
{
    __shared__ float t[32][33];
    const size_t lo_ = (size_t)blockIdx.z * Kd * Nd;
    const float* Wp = W + lo_;
    __half* thp = th + lo_;
    const int n0 = blockIdx.x * 32, k0 = blockIdx.y * 32;
    const int tx = threadIdx.x & 31, ty = threadIdx.x >> 5;

    #pragma unroll
    for (int j = 0; j < 32; j += 8)
        t[ty + j][tx] = Wp[(size_t)(k0 + ty + j) * Nd + n0 + tx];
    __syncthreads();
    #pragma unroll
    for (int j = 0; j < 32; j += 8)
        thp[(size_t)(n0 + ty + j) * Kd + k0 + tx] = __float2half_rn(t[tx][ty + j]);
}

// fused transpose for the four DxD weight families (one launch)
struct W4 { const float* w; __half* th; };
__global__ void wtrans4_kernel(W4 a, W4 b, W4 c, W4 d)
{
    __shared__ float t[32][33];
    const int which = blockIdx.z & 3;
    const int lyr   = blockIdx.z >> 2;
    const W4 s = (which == 0) ? a : (which == 1) ? b : (which == 2) ? c : d;
    const size_t lo_ = (size_t)lyr * D_ * D_;
    const float* Wp = s.w + lo_;
    __half* thp = s.th + lo_;
    const int n0 = blockIdx.x * 32, k0 = blockIdx.y * 32;
    const int tx = threadIdx.x & 31, ty = threadIdx.x >> 5;

    #pragma unroll
    for (int j = 0; j < 32; j += 8)
        t[ty + j][tx] = Wp[(size_t)(k0 + ty + j) * D_ + n0 + tx];
    __syncthreads();
    #pragma unroll
    for (int j = 0; j < 32; j += 8)
        thp[(size_t)(n0 + ty + j) * D_ + k0 + tx] = __float2half_rn(t[tx][ty + j]);
}

// -------------------- positional-encoding table (flat) ----------------------
__global__ void pe_kernel(float* __restrict__ pe)
{
    const int i = blockIdx.x * 256 + threadIdx.x;
    if (i >= S_ * D_) return;
    const int s = i / D_, c = i - s * D_;
    const int j = c >> 1;
    const double e   = (double)(4 * j) / 768.0;
    const double inv = pow(10000.0, -e);
    const float  arg = (float)((double)s * inv);
    pe[i] = (c & 1) ? cosf(arg) : sinf(arg);
}

// -------------------- embedding (fp32 + fp16) -------------------------------
__global__ void embed_kernel(const int* __restrict__ x, const int* __restrict__ seg,
                             const float* __restrict__ tok, const float* __restrict__ se,
                             const float* __restrict__ pe, float* __restrict__ h,
                             __half* __restrict__ sh)
{
    const int t   = blockIdx.x;
    const int tid = threadIdx.x;
    const int s   = t & (S_ - 1);
    const int xi  = x[t];
    const int si  = seg[t];
    const size_t base = (size_t)t * D_;
    #pragma unroll
    for (int u = 0; u < 3; ++u) {
        const int c = tid + u * 256;
        const float v = tok[(size_t)xi * D_ + c] + se[(size_t)si * D_ + c] + pe[s * D_ + c];
        h[base + c] = v;
        sh[base + c] = __float2half_rn(v);
    }
}

// -------------------- fused attention (fp16 in, fp32 math, fp16 out) --------
// grid = B*H (1536), block = 256. Smem reuse: Qs->P, Ks->V after score phase.
__global__ void attn_fused_kernel(const __half* __restrict__ q, const __half* __restrict__ k,
                                  const __half* __restrict__ v, const int* __restrict__ x,
                                  __half* __restrict__ oh)
{
    __shared__ float Qs[S_ * 65];     // phase 1: Q      phase 2: P
    __shared__ float Ks[S_ * 65];     // phase 1: K      phase 2: V (flat 64-stride)
    __shared__ int   mk[S_];

    const int bh = blockIdx.x;
    const int b  = bh / H_;
    const int h  = bh % H_;
    const int tid = threadIdx.x;

    const __half* qbase = q + (size_t)(b * S_) * D_ + h * DK_;
    const __half* kbase = k + (size_t)(b * S_) * D_ + h * DK_;
    const __half* vbase = v + (size_t)(b * S_) * D_ + h * DK_;

    for (int idx = tid; idx < S_ * DK_; idx += 256) {
        const int r = idx >> 6, d = idx & 63;
        Qs[r * 65 + d] = __half2float(qbase[(size_t)r * D_ + d]);
        Ks[r * 65 + d] = __half2float(kbase[(size_t)r * D_ + d]);
    }
    if (tid < S_) mk[tid] = x[b * S_ + tid];
    __syncthreads();

    const int row = tid >> 2;          // query row 0..63
    const int jc  = (tid & 3) * 16;    // key-col block

    float sc[16];
    #pragma unroll
    for (int jj = 0; jj < 16; ++jj) sc[jj] = 0.0f;

    for (int d = 0; d < DK_; ++d) {
        const float qv = Qs[row * 65 + d];
        #pragma unroll
        for (int jj = 0; jj < 16; ++jj)
            sc[jj] += qv * Ks[(jc + jj) * 65 + d];
    }

    float mx = -3.0e38f;
    #pragma unroll
    for (int jj = 0; jj < 16; ++jj) {
        const float val = (mk[jc + jj] > 0) ? sc[jj] * 0.125f : -1.0e9f;
        sc[jj] = val;
        mx = fmaxf(mx, val);
    }
    mx = fmaxf(mx, __shfl_xor_sync(0xffffffffu, mx, 1));
    mx = fmaxf(mx, __shfl_xor_sync(0xffffffffu, mx, 2));

    float sum = 0.0f;
    #pragma unroll
    for (int jj = 0; jj < 16; ++jj) {
        sc[jj] = expf(sc[jj] - mx);
        sum += sc[jj];
    }
    sum += __shfl_xor_sync(0xffffffffu, sum, 1);
    sum += __shfl_xor_sync(0xffffffffu, sum, 2);
    const float pinv = 1.0f / sum;

    __syncthreads();   // all Qs/Ks reads of phase 1 complete

    // write P into Qs, load V into Ks (flat, stride 64)
    #pragma unroll
    for (int jj = 0; jj < 16; ++jj) Qs[row * 65 + jc + jj] = sc[jj] * pinv;
    for (int idx = tid; idx < S_ * DK_; idx += 256)
        Ks[idx] = __half2float(vbase[(size_t)(idx >> 6) * D_ + (idx & 63)]);
    __syncthreads();

    // ctx = P @ V : thread owns (row, 16 headdims at d0)
    const int d0 = (tid & 3) * 16;
    float acc[16];
    #pragma unroll
    for (int dd = 0; dd < 16; ++dd) acc[dd] = 0.0f;

    for (int j = 0; j < S_; ++j) {
        const float p = Qs[row * 65 + j];
        #pragma unroll
        for (int dd = 0; dd < 16; ++dd)
            acc[dd] += p * Ks[j * DK_ + d0 + dd];
    }

    const size_t obase = (size_t)(b * S_ + row) * D_ + h * DK_ + d0;
    #pragma unroll
    for (int dd = 0; dd < 16; dd += 2) {
        __half2 hb;
        hb.x = __float2half_rn(acc[dd]);
        hb.y = __float2half_rn(acc[dd + 1]);
        *(__half2*)(oh + obase + dd) = hb;
    }
}

// -------------------- residual add + layernorm (fp32 + fp16) ----------------
__global__ void resid_ln_kernel(const float* __restrict__ a, const float* __restrict__ r,
                                const float* __restrict__ g, const float* __restrict__ be,
                                float* __restrict__ out, __half* __restrict__ oh)
{
    const int t   = blockIdx.x;
    const int tid = threadIdx.x;
    const size_t base = (size_t)t * D_;

    const float y0 = a[base + tid]       + r[base + tid];
    const float y1 = a[base + tid + 256] + r[base + tid + 256];
    const float y2 = a[base + tid + 512] + r[base + tid + 512];

    __shared__ float red[256];
    red[tid] = y0 + y1 + y2;
    __syncthreads();
    #pragma unroll
    for (int o = 128; o > 0; o >>= 1) {
        if (tid < o) red[tid] += red[tid + o];
        __syncthreads();
    }
    const float mu = red[0] * (1.0f / 768.0f);
    __syncthreads();

    const float d0 = y0 - mu, d1 = y1 - mu, d2 = y2 - mu;
    red[tid] = d0 * d0 + d1 * d1 + d2 * d2;
    __syncthreads();
    #pragma unroll
    for (int o = 128; o > 0; o >>= 1) {
        if (tid < o) red[tid] += red[tid + o];
        __syncthreads();
    }
    const float var = red[0] * (1.0f / 768.0f);
    const float inv = rsqrtf(var + 1e-5f);

    const float o0 = d0 * inv * g[tid]       + be[tid];
    const float o1 = d1 * inv * g[tid + 256] + be[tid + 256];
    const float o2 = d2 * inv * g[tid + 512] + be[tid + 512];
    out[base + tid]       = o0;
    out[base + tid + 256] = o1;
    out[base + tid + 512] = o2;
    oh[base + tid]        = __float2half_rn(o0);
    oh[base + tid + 256]  = __float2half_rn(o1);
    oh[base + tid + 512]  = __float2half_rn(o2);
}

// ---------------------------------------------------------------------------
extern "C" void kernel_launch(void* const* d_in, const int* in_sizes, int n_in,
                              void* d_out, int out_size)
{
    const int*   x    = (const int*)  d_in[0];
    const int*   seg  = (const int*)  d_in[1];
    const float* tok  = (const float*)d_in[2];
    const float* se   = (const float*)d_in[3];
    const float* Wq   = (const float*)d_in[4];
    const float* bq   = (const float*)d_in[5];
    const float* Wk   = (const float*)d_in[6];
    const float* bk   = (const float*)d_in[7];
    const float* Wv   = (const float*)d_in[8];
    const float* bv   = (const float*)d_in[9];
    const float* Wo   = (const float*)d_in[10];
    const float* bo   = (const float*)d_in[11];
    const float* lng  = (const float*)d_in[12];
    const float* lnb  = (const float*)d_in[13];
    const float* W1   = (const float*)d_in[14];
    const float* b1   = (const float*)d_in[15];
    const float* W2   = (const float*)d_in[16];
    const float* b2   = (const float*)d_in[17];
    float* out = (float*)d_out;

    float *h, *h1, *tmp, *pe;
    __half *ah, *sh, *qh, *kh, *vh;
    __half *wq, *wk, *wv, *wo, *w1, *w2;
    cudaGetSymbolAddress((void**)&h,   g_h);
    cudaGetSymbolAddress((void**)&h1,  g_h1);
    cudaGetSymbolAddress((void**)&tmp, g_tmp);
    cudaGetSymbolAddress((void**)&pe,  g_pe);
    cudaGetSymbolAddress((void**)&ah,  g_ah);
    cudaGetSymbolAddress((void**)&sh,  g_sh);
    cudaGetSymbolAddress((void**)&qh,  g_qh);
    cudaGetSymbolAddress((void**)&kh,  g_kh);
    cudaGetSymbolAddress((void**)&vh,  g_vh);
    cudaGetSymbolAddress((void**)&wq,  g_wq);
    cudaGetSymbolAddress((void**)&wk,  g_wk);
    cudaGetSymbolAddress((void**)&wv,  g_wv);
    cudaGetSymbolAddress((void**)&wo,  g_wo);
    cudaGetSymbolAddress((void**)&w1,  g_w1);
    cudaGetSymbolAddress((void**)&w2,  g_w2);

    cudaFuncSetAttribute(gemm_kernel<false>, cudaFuncAttributeMaxDynamicSharedMemorySize, GSMEM_);
    cudaFuncSetAttribute(gemm_kernel<true >, cudaFuncAttributeMaxDynamicSharedMemorySize, GSMEM_);

    // ---- setup ----
    {
        W4 aq = { Wq, wq }, ak = { Wk, wk }, av = { Wv, wv }, ao = { Wo, wo };
        wtrans4_kernel<<<dim3(24, 24, 4 * L_), 256>>>(aq, ak, av, ao);
    }
    wtrans_kernel<<<dim3(96, 24, L_), 256>>>(W1, w1, D_, FF_);
    wtrans_kernel<<<dim3(24, 96, L_), 256>>>(W2, w2, FF_, D_);
    pe_kernel<<<(S_ * D_ + 255) / 256, 256>>>(pe);
    embed_kernel<<<NT_, 256>>>(x, seg, tok, se, pe, h, sh);

    const dim3 gP(D_ / BN_, NT_ / BM_, 1);    // (6, 64)  N=768 GEMMs
    const dim3 gQKV(D_ / BN_, NT_ / BM_, 3);  // fused QKV
    const dim3 gF(FF_ / BN_, NT_ / BM_, 1);   // (24, 64) FF1

    for (int l = 0; l < L_; ++l) {
        const size_t wOff  = (size_t)l * D_ * D_;
        const size_t fOff1 = (size_t)l * D_ * FF_;
        const size_t fOff2 = (size_t)l * FF_ * D_;

        {   // QKV from fp16 h -> fp16 q/k/v
            BOp oq = { wq + wOff, bq + l * D_, nullptr, qh };
            BOp ok = { wk + wOff, bk + l * D_, nullptr, kh };
            BOp ov = { wv + wOff, bv + l * D_, nullptr, vh };
            gemm_kernel<false><<<gQKV, GT_, GSMEM_>>>(sh, oq, ok, ov, D_, D_);
        }

        attn_fused_kernel<<<B_ * H_, 256>>>(qh, kh, vh, x, sh);   // fp16 ctx

        {   // O projection from fp16 ctx -> fp32 tmp
            BOp oo = { wo + wOff, bo + l * D_, tmp, nullptr };
            gemm_kernel<false><<<gP, GT_, GSMEM_>>>(sh, oo, oo, oo, D_, D_);
        }
        resid_ln_kernel<<<NT_, 256>>>(tmp, h, lng + l * D_, lnb + l * D_, h1, sh);

        {   // FF1 (+GELU) from fp16 h1 -> fp16 ff
            BOp o1 = { w1 + fOff1, b1 + l * FF_, nullptr, ah };
            gemm_kernel<true><<<gF, GT_, GSMEM_>>>(sh, o1, o1, o1, D_, FF_);
        }
        {   // FF2 from fp16 ff -> fp32 tmp
            BOp o2 = { w2 + fOff2, b2 + l * D_, tmp, nullptr };
            gemm_kernel<false><<<gP, GT_, GSMEM_>>>(ah, o2, o2, o2, FF_, D_);
        }

        float* dst = (l == L_ - 1) ? out : h;
        resid_ln_kernel<<<NT_, 256>>>(tmp, h1, lng + l * D_, lnb + l * D_, dst, sh);
    }
}

// round 17
// speedup vs baseline: 1.0941x; 1.0395x over previous
#include <cuda_runtime.h>
#include <cuda_fp16.h>
#include <math.h>
#include <stdint.h>

// ---------------------------------------------------------------------------
// BERT-base forward (B=128, S=64, D=768, H=12, L=12, FF=3072).
// GEMMs: mma.sync (HMMA) plain fp16 1-pass, fp32 accumulators.
// 3-stage cp.async pipeline, ONE __syncthreads per K-chunk (CUTLASS rotation).
// 256 thr, 128x128x64 tiles, 2 CTAs/SM. QKV/ctx/h1/ff all fp16.
// Attention / LayerNorm / embedding: fp32 CUDA-core kernels.
// ---------------------------------------------------------------------------

#define B_    128
#define S_    64
#define D_    768
#define H_    12
#define DK_   64
#define FF_   3072
#define L_    12
#define NT_   (B_ * S_)          // 8192 tokens

// -------------------- scratch (device globals; no allocs) -------------------
__device__ float g_h   [NT_ * D_];
__device__ float g_h1  [NT_ * D_];
__device__ float g_tmp [NT_ * D_];
__device__ float g_pe  [S_ * D_];

// fp16 activations
__device__ __half g_ah[NT_ * FF_];   // FF1 output
__device__ __half g_sh[NT_ * D_];    // h / ctx / h1 fp16 mirror
__device__ __half g_qh[NT_ * D_];
__device__ __half g_kh[NT_ * D_];
__device__ __half g_vh[NT_ * D_];

// fp16 transposed weights: [L][N][K] layout (K contiguous per row)
__device__ __half g_wq[L_ * D_ * D_];
__device__ __half g_wk[L_ * D_ * D_];
__device__ __half g_wv[L_ * D_ * D_];
__device__ __half g_wo[L_ * D_ * D_];
__device__ __half g_w1[L_ * FF_ * D_];   // [L][3072][768]
__device__ __half g_w2[L_ * D_ * FF_];   // [L][768][3072]

// -------------------- PTX helpers (all arch-agnostic, sm_80+) ---------------
__device__ __forceinline__ uint32_t smem_u32(const void* p) {
    uint32_t a;
    asm("{ .reg .u64 t; cvta.to.shared.u64 t, %1; cvt.u32.u64 %0, t; }"
        : "=r"(a) : "l"(p));
    return a;
}
__device__ __forceinline__ void cp16(uint32_t s, const void* g) {
    asm volatile("cp.async.cg.shared.global [%0], [%1], 16;" :: "r"(s), "l"(g) : "memory");
}
__device__ __forceinline__ void ldsm4(uint32_t& r0, uint32_t& r1, uint32_t& r2,
                                      uint32_t& r3, uint32_t a) {
    asm volatile("ldmatrix.sync.aligned.m8n8.x4.shared.b16 {%0,%1,%2,%3}, [%4];"
                 : "=r"(r0), "=r"(r1), "=r"(r2), "=r"(r3) : "r"(a));
}
__device__ __forceinline__ void mma16816(float* c, const uint32_t* a,
                                         uint32_t b0, uint32_t b1) {
    asm volatile("mma.sync.aligned.m16n8k16.row.col.f32.f16.f16.f32 "
                 "{%0,%1,%2,%3}, {%4,%5,%6,%7}, {%8,%9}, {%0,%1,%2,%3};"
                 : "+f"(c[0]), "+f"(c[1]), "+f"(c[2]), "+f"(c[3])
                 : "r"(a[0]), "r"(a[1]), "r"(a[2]), "r"(a[3]), "r"(b0), "r"(b1));
}

// -------------------- HMMA fp16 1-pass GEMM (3-stage, 1 sync/chunk) ---------
// C[8192, N] = A[8192, K] @ W[K, N] + bias (+GELU). A, W fp16; W transposed
// to Bt[N, K]. CTA tile 128x128, BK=64. Output fp32 (op.c) and/or fp16 (op.oh).
struct BOp { const __half* bt; const float* bias; float* c; __half* oh; };

#define GT_       256
#define BM_       128
#define BN_       128
#define BK_       64
#define TILE_B_   16384u       // 128 rows x 128 bytes
#define STAGE_B_  32768u       // A, B
#define NSTAGE_   3
#define GSMEM_    (NSTAGE_ * 32768)

template <bool GELU>
__global__ __launch_bounds__(GT_, 2)
void gemm_kernel(const __half* __restrict__ A,
                 BOp op0, BOp op1, BOp op2, int K, int N)
{
    extern __shared__ char smem[];
    const uint32_t sb = smem_u32(smem);
    const int tid = threadIdx.x, wid = tid >> 5, l = tid & 31;
    const int wm = wid & 1;          // 2 warps along M
    const int wn = wid >> 1;         // 4 warps along N
    const BOp op = (blockIdx.z == 0) ? op0 : ((blockIdx.z == 1) ? op1 : op2);
    const int m0 = blockIdx.y * BM_;
    const int n0 = blockIdx.x * BN_;

    // per-lane ldmatrix addressing components
    const uint32_t swz  = (uint32_t)((l & 7) << 4);
    const int aRow0     = wm * 64 + ((l >> 3) & 1) * 8 + (l & 7);
    const uint32_t aSel = (uint32_t)(((l >> 4) & 1) * 16);
    const int bRow0     = wn * 32 + ((l >> 4) & 1) * 8 + (l & 7);
    const uint32_t bSel = (uint32_t)(((l >> 3) & 1) * 16);

    float acc[4][4][4];
    #pragma unroll
    for (int i = 0; i < 4; ++i)
        #pragma unroll
        for (int j = 0; j < 4; ++j)
            #pragma unroll
            for (int e = 0; e < 4; ++e) acc[i][j][e] = 0.0f;

    const int nch = K / BK_;     // 12 or 48 (always >= 2)

    // ---- async prefetch of one stage (A|B tiles): 8 cp16/thread ----
    auto prefetch = [&](int c, int s) {
        const int kc = c * BK_;
        const uint32_t sbase = sb + (uint32_t)s * STAGE_B_;
        #pragma unroll 4
        for (int g = tid; g < 2048; g += GT_) {
            const int t   = g >> 10;                 // 0=A, 1=B
            const int idx = g & 1023;
            const int row = idx >> 3, seg = idx & 7;
            const uint32_t sa = sbase + (uint32_t)t * TILE_B_ + (uint32_t)row * 128
                              + (((uint32_t)(seg * 16)) ^ ((uint32_t)(row & 7) << 4));
            const __half* src;
            if (t == 0) src = A     + (size_t)(m0 + row) * K + kc + seg * 8;
            else        src = op.bt + (size_t)(n0 + row) * K + kc + seg * 8;
            cp16(sa, src);
        }
        asm volatile("cp.async.commit_group;" ::: "memory");
    };

    // prologue: fill stages 0 and 1
    prefetch(0, 0);
    prefetch(1, 1);

    int sp = 2;      // next prefetch stage
    int sc = 0;      // compute stage

    for (int c = 0; c < nch; ++c) {
        // wait for chunk c's group: pending = {c, c+1} unless last chunk
        if (c == nch - 1) {
            asm volatile("cp.async.wait_group 0;" ::: "memory");
        } else {
            asm volatile("cp.async.wait_group 1;" ::: "memory");
        }
        __syncthreads();   // single barrier per chunk: all warps done chunk c-1

        // prefetch chunk c+2 into stage (c-1)%3 — safe past the barrier
        if (c + 2 < nch) {
            prefetch(c + 2, sp);
            sp = (sp + 1 == NSTAGE_) ? 0 : sp + 1;
        }

        const uint32_t sbase = sb + (uint32_t)sc * STAGE_B_;
        sc = (sc + 1 == NSTAGE_) ? 0 : sc + 1;

        #pragma unroll
        for (int ks = 0; ks < 4; ++ks) {
            const uint32_t aCol = ((uint32_t)(ks * 32) + aSel) ^ swz;
            const uint32_t bCol = ((uint32_t)(ks * 32) + bSel) ^ swz;
            uint32_t a[4][4];
            #pragma unroll
            for (int mb = 0; mb < 4; ++mb)
                ldsm4(a[mb][0], a[mb][1], a[mb][2], a[mb][3],
                      sbase + (uint32_t)(aRow0 + mb * 16) * 128 + aCol);
            #pragma unroll
            for (int nb = 0; nb < 2; ++nb) {
                uint32_t b0, b1, b2, b3;
                ldsm4(b0, b1, b2, b3,
                      sbase + TILE_B_ + (uint32_t)(bRow0 + nb * 16) * 128 + bCol);
                #pragma unroll
                for (int mb = 0; mb < 4; ++mb) {
                    mma16816(acc[mb][nb * 2 + 0], a[mb], b0, b1);
                    mma16816(acc[mb][nb * 2 + 1], a[mb], b2, b3);
                }
            }
        }
    }

    // ---- epilogue: bias (+GELU), fp32 and/or fp16 stores ----
    const int rbase = m0 + wm * 64 + (l >> 2);
    const int cbase = n0 + wn * 32 + (l & 3) * 2;
    #pragma unroll
    for (int mb = 0; mb < 4; ++mb) {
        #pragma unroll
        for (int nblk = 0; nblk < 4; ++nblk) {
            const int col = cbase + nblk * 8;
            const float bx = op.bias[col], by = op.bias[col + 1];
            float v[4] = { acc[mb][nblk][0] + bx, acc[mb][nblk][1] + by,
                           acc[mb][nblk][2] + bx, acc[mb][nblk][3] + by };
            if (GELU) {
                #pragma unroll
                for (int e = 0; e < 4; ++e)
                    v[e] = 0.5f * v[e] * (1.0f + erff(v[e] * 0.70710678118654752440f));
            }
            const int row = rbase + mb * 16;
            if (op.c) {
                float2 lo; lo.x = v[0]; lo.y = v[1];
                float2 hi; hi.x = v[2]; hi.y = v[3];
                *(float2*)(op.c + (size_t)row * N + col)       = lo;
                *(float2*)(op.c + (size_t)(row + 8) * N + col) = hi;
            }
            if (op.oh) {
                __half2 h0, h1;
                h0.x = __float2half_rn(v[0]);
                h0.y = __float2half_rn(v[1]);
                h1.x = __float2half_rn(v[2]);
                h1.y = __float2half_rn(v[3]);
                *(__half2*)(op.oh + (size_t)row * N + col)       = h0;
                *(__half2*)(op.oh + (size_t)(row + 8) * N + col) = h1;
            }
        }
    }
}

// -------------------- weight transpose -> fp16 ------------------------------
__global__ void wtrans_kernel(const float* __restrict__ W,
                              __half* __restrict__ th, int Kd, int Nd)
{
    __shared__ float t[32][33];
    const size_t lo_ = (size_t)blockIdx.z * Kd * Nd;
    const float* Wp = W + lo_;
    __half* thp = th + lo_;
    const int n0 = blockIdx.x * 32, k0 = blockIdx.y * 32;
    const int tx = threadIdx.x & 31, ty = threadIdx.x >> 5;

    #pragma unroll
    for (int j = 0; j < 32; j += 8)
        t[ty + j][tx] = Wp[(size_t)(k0 + ty + j) * Nd + n0 + tx];
    __syncthreads();
    #pragma unroll
    for (int j = 0; j < 32; j += 8)
        thp[(size_t)(n0 + ty + j) * Kd + k0 + tx] = __float2half_rn(t[tx][ty + j]);
}

// fused transpose for the four DxD weight families (one launch)
struct W4 { const float* w; __half* th; };
__global__ void wtrans4_kernel(W4 a, W4 b, W4 c, W4 d)
{
    __shared__ float t[32][33];
    const int which = blockIdx.z & 3;
    const int lyr   = blockIdx.z >> 2;
    const W4 s = (which == 0) ? a : (which == 1) ? b : (which == 2) ? c : d;
    const size_t lo_ = (size_t)lyr * D_ * D_;
    const float* Wp = s.w + lo_;
    __half* thp = s.th + lo_;
    const int n0 = blockIdx.x * 32, k0 = blockIdx.y * 32;
    const int tx = threadIdx.x & 31, ty = threadIdx.x >> 5;

    #pragma unroll
    for (int j = 0; j < 32; j += 8)
        t[ty + j][tx] = Wp[(size_t)(k0 + ty + j) * D_ + n0 + tx];
    __syncthreads();
    #pragma unroll
    for (int j = 0; j < 32; j += 8)
        thp[(size_t)(n0 + ty + j) * D_ + k0 + tx] = __float2half_rn(t[tx][ty + j]);
}

// -------------------- positional-encoding table (flat) ----------------------
__global__ void pe_kernel(float* __restrict__ pe)
{
    const int i = blockIdx.x * 256 + threadIdx.x;
    if (i >= S_ * D_) return;
    const int s = i / D_, c = i - s * D_;
    const int j = c >> 1;
    const double e   = (double)(4 * j) / 768.0;
    const double inv = pow(10000.0, -e);
    const float  arg = (float)((double)s * inv);
    pe[i] = (c & 1) ? cosf(arg) : sinf(arg);
}

// -------------------- embedding (fp32 + fp16) -------------------------------
__global__ void embed_kernel(const int* __restrict__ x, const int* __restrict__ seg,
                             const float* __restrict__ tok, const float* __restrict__ se,
                             const float* __restrict__ pe, float* __restrict__ h,
                             __half* __restrict__ sh)
{
    const int t   = blockIdx.x;
    const int tid = threadIdx.x;
    const int s   = t & (S_ - 1);
    const int xi  = x[t];
    const int si  = seg[t];
    const size_t base = (size_t)t * D_;
    #pragma unroll
    for (int u = 0; u < 3; ++u) {
        const int c = tid + u * 256;
        const float v = tok[(size_t)xi * D_ + c] + se[(size_t)si * D_ + c] + pe[s * D_ + c];
        h[base + c] = v;
        sh[base + c] = __float2half_rn(v);
    }
}

// -------------------- fused attention (fp16 in, fp32 math, fp16 out) --------
// grid = B*H (1536), block = 256. Smem reuse: Qs->P, Ks->V after score phase.
__global__ void attn_fused_kernel(const __half* __restrict__ q, const __half* __restrict__ k,
                                  const __half* __restrict__ v, const int* __restrict__ x,
                                  __half* __restrict__ oh)
{
    __shared__ float Qs[S_ * 65];     // phase 1: Q      phase 2: P
    __shared__ float Ks[S_ * 65];     // phase 1: K      phase 2: V (flat 64-stride)
    __shared__ int   mk[S_];

    const int bh = blockIdx.x;
    const int b  = bh / H_;
    const int h  = bh % H_;
    const int tid = threadIdx.x;

    const __half* qbase = q + (size_t)(b * S_) * D_ + h * DK_;
    const __half* kbase = k + (size_t)(b * S_) * D_ + h * DK_;
    const __half* vbase = v + (size_t)(b * S_) * D_ + h * DK_;

    for (int idx = tid; idx < S_ * DK_; idx += 256) {
        const int r = idx >> 6, d = idx & 63;
        Qs[r * 65 + d] = __half2float(qbase[(size_t)r * D_ + d]);
        Ks[r * 65 + d] = __half2float(kbase[(size_t)r * D_ + d]);
    }
    if (tid < S_) mk[tid] = x[b * S_ + tid];
    __syncthreads();

    const int row = tid >> 2;          // query row 0..63
    const int jc  = (tid & 3) * 16;    // key-col block

    float sc[16];
    #pragma unroll
    for (int jj = 0; jj < 16; ++jj) sc[jj] = 0.0f;

    for (int d = 0; d < DK_; ++d) {
        const float qv = Qs[row * 65 + d];
        #pragma unroll
        for (int jj = 0; jj < 16; ++jj)
            sc[jj] += qv * Ks[(jc + jj) * 65 + d];
    }

    float mx = -3.0e38f;
    #pragma unroll
    for (int jj = 0; jj < 16; ++jj) {
        const float val = (mk[jc + jj] > 0) ? sc[jj] * 0.125f : -1.0e9f;
        sc[jj] = val;
        mx = fmaxf(mx, val);
    }
    mx = fmaxf(mx, __shfl_xor_sync(0xffffffffu, mx, 1));
    mx = fmaxf(mx, __shfl_xor_sync(0xffffffffu, mx, 2));

    float sum = 0.0f;
    #pragma unroll
    for (int jj = 0; jj < 16; ++jj) {
        sc[jj] = expf(sc[jj] - mx);
        sum += sc[jj];
    }
    sum += __shfl_xor_sync(0xffffffffu, sum, 1);
    sum += __shfl_xor_sync(0xffffffffu, sum, 2);
    const float pinv = 1.0f / sum;

    __syncthreads();   // all Qs/Ks reads of phase 1 complete

    // write P into Qs, load V into Ks (flat, stride 64)
    #pragma unroll
    for (int jj = 0; jj < 16; ++jj) Qs[row * 65 + jc + jj] = sc[jj] * pinv;
    for (int idx = tid; idx < S_ * DK_; idx += 256)
        Ks[idx] = __half2float(vbase[(size_t)(idx >> 6) * D_ + (idx & 63)]);
    __syncthreads();

    // ctx = P @ V : thread owns (row, 16 headdims at d0)
    const int d0 = (tid & 3) * 16;
    float acc[16];
    #pragma unroll
    for (int dd = 0; dd < 16; ++dd) acc[dd] = 0.0f;

    for (int j = 0; j < S_; ++j) {
        const float p = Qs[row * 65 + j];
        #pragma unroll
        for (int dd = 0; dd < 16; ++dd)
            acc[dd] += p * Ks[j * DK_ + d0 + dd];
    }

    const size_t obase = (size_t)(b * S_ + row) * D_ + h * DK_ + d0;
    #pragma unroll
    for (int dd = 0; dd < 16; dd += 2) {
        __half2 hb;
        hb.x = __float2half_rn(acc[dd]);
        hb.y = __float2half_rn(acc[dd + 1]);
        *(__half2*)(oh + obase + dd) = hb;
    }
}

// -------------------- residual add + layernorm (shuffle reduce) -------------
__global__ void resid_ln_kernel(const float* __restrict__ a, const float* __restrict__ r,
                                const float* __restrict__ g, const float* __restrict__ be,
                                float* __restrict__ out, __half* __restrict__ oh)
{
    const int t   = blockIdx.x;
    const int tid = threadIdx.x;
    const int wid = tid >> 5, lid = tid & 31;
    const size_t base = (size_t)t * D_;

    const float y0 = a[base + tid]       + r[base + tid];
    const float y1 = a[base + tid + 256] + r[base + tid + 256];
    const float y2 = a[base + tid + 512] + r[base + tid + 512];

    __shared__ float red1[8], red2[8];

    // mean: warp shuffle tree, then 8 partials
    float ps = y0 + y1 + y2;
    #pragma unroll
    for (int o = 16; o > 0; o >>= 1) ps += __shfl_xor_sync(0xffffffffu, ps, o);
    if (lid == 0) red1[wid] = ps;
    __syncthreads();
    float mu = (red1[0] + red1[1] + red1[2] + red1[3] +
                red1[4] + red1[5] + red1[6] + red1[7]) * (1.0f / 768.0f);

    const float d0 = y0 - mu, d1 = y1 - mu, d2 = y2 - mu;
    float pv = d0 * d0 + d1 * d1 + d2 * d2;
    #pragma unroll
    for (int o = 16; o > 0; o >>= 1) pv += __shfl_xor_sync(0xffffffffu, pv, o);
    if (lid == 0) red2[wid] = pv;
    __syncthreads();
    const float var = (red2[0] + red2[1] + red2[2] + red2[3] +
                       red2[4] + red2[5] + red2[6] + red2[7]) * (1.0f / 768.0f);
    const float inv = rsqrtf(var + 1e-5f);

    const float o0 = d0 * inv * g[tid]       + be[tid];
    const float o1 = d1 * inv * g[tid + 256] + be[tid + 256];
    const float o2 = d2 * inv * g[tid + 512] + be[tid + 512];
    out[base + tid]       = o0;
    out[base + tid + 256] = o1;
    out[base + tid + 512] = o2;
    oh[base + tid]        = __float2half_rn(o0);
    oh[base + tid + 256]  = __float2half_rn(o1);
    oh[base + tid + 512]  = __float2half_rn(o2);
}

// ---------------------------------------------------------------------------
extern "C" void kernel_launch(void* const* d_in, const int* in_sizes, int n_in,
                              void* d_out, int out_size)
{
    const int*   x    = (const int*)  d_in[0];
    const int*   seg  = (const int*)  d_in[1];
    const float* tok  = (const float*)d_in[2];
    const float* se   = (const float*)d_in[3];
    const float* Wq   = (const float*)d_in[4];
    const float* bq   = (const float*)d_in[5];
    const float* Wk   = (const float*)d_in[6];
    const float* bk   = (const float*)d_in[7];
    const float* Wv   = (const float*)d_in[8];
    const float* bv   = (const float*)d_in[9];
    const float* Wo   = (const float*)d_in[10];
    const float* bo   = (const float*)d_in[11];
    const float* lng  = (const float*)d_in[12];
    const float* lnb  = (const float*)d_in[13];
    const float* W1   = (const float*)d_in[14];
    const float* b1   = (const float*)d_in[15];
    const float* W2   = (const float*)d_in[16];
    const float* b2   = (const float*)d_in[17];
    float* out = (float*)d_out;

    float *h, *h1, *tmp, *pe;
    __half *ah, *sh, *qh, *kh, *vh;
    __half *wq, *wk, *wv, *wo, *w1, *w2;
    cudaGetSymbolAddress((void**)&h,   g_h);
    cudaGetSymbolAddress((void**)&h1,  g_h1);
    cudaGetSymbolAddress((void**)&tmp, g_tmp);
    cudaGetSymbolAddress((void**)&pe,  g_pe);
    cudaGetSymbolAddress((void**)&ah,  g_ah);
    cudaGetSymbolAddress((void**)&sh,  g_sh);
    cudaGetSymbolAddress((void**)&qh,  g_qh);
    cudaGetSymbolAddress((void**)&kh,  g_kh);
    cudaGetSymbolAddress((void**)&vh,  g_vh);
    cudaGetSymbolAddress((void**)&wq,  g_wq);
    cudaGetSymbolAddress((void**)&wk,  g_wk);
    cudaGetSymbolAddress((void**)&wv,  g_wv);
    cudaGetSymbolAddress((void**)&wo,  g_wo);
    cudaGetSymbolAddress((void**)&w1,  g_w1);
    cudaGetSymbolAddress((void**)&w2,  g_w2);

    cudaFuncSetAttribute(gemm_kernel<false>, cudaFuncAttributeMaxDynamicSharedMemorySize, GSMEM_);
    cudaFuncSetAttribute(gemm_kernel<true >, cudaFuncAttributeMaxDynamicSharedMemorySize, GSMEM_);

    // ---- setup ----
    {
        W4 aq = { Wq, wq }, ak = { Wk, wk }, av = { Wv, wv }, ao = { Wo, wo };
        wtrans4_kernel<<<dim3(24, 24, 4 * L_), 256>>>(aq, ak, av, ao);
    }
    wtrans_kernel<<<dim3(96, 24, L_), 256>>>(W1, w1, D_, FF_);
    wtrans_kernel<<<dim3(24, 96, L_), 256>>>(W2, w2, FF_, D_);
    pe_kernel<<<(S_ * D_ + 255) / 256, 256>>>(pe);
    embed_kernel<<<NT_, 256>>>(x, seg, tok, se, pe, h, sh);

    const dim3 gP(D_ / BN_, NT_ / BM_, 1);    // (6, 64)  N=768 GEMMs
    const dim3 gQKV(D_ / BN_, NT_ / BM_, 3);  // fused QKV
    const dim3 gF(FF_ / BN_, NT_ / BM_, 1);   // (24, 64) FF1

    for (int l = 0; l < L_; ++l) {
        const size_t wOff  = (size_t)l * D_ * D_;
        const size_t fOff1 = (size_t)l * D_ * FF_;
        const size_t fOff2 = (size_t)l * FF_ * D_;

        {   // QKV from fp16 h -> fp16 q/k/v
            BOp oq = { wq + wOff, bq + l * D_, nullptr, qh };
            BOp ok = { wk + wOff, bk + l * D_, nullptr, kh };
            BOp ov = { wv + wOff, bv + l * D_, nullptr, vh };
            gemm_kernel<false><<<gQKV, GT_, GSMEM_>>>(sh, oq, ok, ov, D_, D_);
        }

        attn_fused_kernel<<<B_ * H_, 256>>>(qh, kh, vh, x, sh);   // fp16 ctx

        {   // O projection from fp16 ctx -> fp32 tmp
            BOp oo = { wo + wOff, bo + l * D_, tmp, nullptr };
            gemm_kernel<false><<<gP, GT_, GSMEM_>>>(sh, oo, oo, oo, D_, D_);
        }
        resid_ln_kernel<<<NT_, 256>>>(tmp, h, lng + l * D_, lnb + l * D_, h1, sh);

        {   // FF1 (+GELU) from fp16 h1 -> fp16 ff
            BOp o1 = { w1 + fOff1, b1 + l * FF_, nullptr, ah };
            gemm_kernel<true><<<gF, GT_, GSMEM_>>>(sh, o1, o1, o1, D_, FF_);
        }
        {   // FF2 from fp16 ff -> fp32 tmp
            BOp o2 = { w2 + fOff2, b2 + l * D_, tmp, nullptr };
            gemm_kernel<false><<<gP, GT_, GSMEM_>>>(ah, o2, o2, o2, FF_, D_);
        }

        float* dst = (l == L_ - 1) ? out : h;
        resid_ln_kernel<<<NT_, 256>>>(tmp, h1, lng + l * D_, lnb + l * D_, dst, sh);
    }
}